// round 16
// baseline (speedup 1.0000x reference)
#include <cuda_runtime.h>
#include <math.h>

// Problem-fixed dims
#define NN 100000
#define IN_X 32
#define IN_E 64
#define HID 128
#define OUT 64

// ---- folded weights (computed by k_prep every launch; deterministic) ----
__device__ __align__(16) float g_W0l[IN_X * HID];  // W0 @ W1l
__device__ __align__(16) float g_W0r[IN_X * HID];  // W0 @ W1r
__device__ __align__(16) float g_c0l[HID];         // b0 @ W1l (gated by cnt>0)
__device__ __align__(16) float g_c1[HID];          // b1l + b0 @ W1r
__device__ __align__(16) float g_val[HID];         // W2l @ Wp[0:64]
__device__ __align__(16) float g_vbl[HID];         // W2l @ Wp[64:128]
__device__ __align__(16) float g_var[HID];         // W2r @ Wp[0:64]
__device__ __align__(16) float g_vbr[HID];         // W2r @ Wp[64:128]
__device__ float g_cab[2];   // b2l.Wpa + bp, b2l.Wpb   (bp folded in)

// ---- per-node scratch ----
__device__ __align__(16) float g_ssumx[NN * IN_X]; // scatter of raw x
__device__ __align__(16) float g_cnt[NN];
__device__ __align__(16) float g_pq[2 * NN];       // p,q  -> scatter source
__device__ __align__(16) float g_r[2 * NN];        // ra,rb (self term)
__device__ __align__(16) float g_spq[2 * NN];      // scattered sums of p,q
__device__ __align__(16) float g_ab[2 * NN];       // final per-node scalars

// ---------------------------------------------------------------------------
// Prep + zero fused: blocks 0-3 fold weights; blocks >=4 zero accumulators.
// ---------------------------------------------------------------------------
__global__ void k_prep_zero(const float* __restrict__ W0, const float* __restrict__ b0,
                            const float* __restrict__ W1l, const float* __restrict__ b1l,
                            const float* __restrict__ W1r,
                            const float* __restrict__ W2l, const float* __restrict__ b2l,
                            const float* __restrict__ W2r,
                            const float* __restrict__ Wp, const float* __restrict__ bp,
                            int N) {
    int b = blockIdx.x;
    int j = threadIdx.x;   // 0..127
    if (b >= 4) {
        int i = (b - 4) * 128 + j;
        int stride = (gridDim.x - 4) * 128;
        int n1 = (N * IN_X) / 4;
        float4 z = make_float4(0.f, 0.f, 0.f, 0.f);
        float4* p1 = reinterpret_cast<float4*>(g_ssumx);
        for (int k = i; k < n1; k += stride) p1[k] = z;
        for (int k = i; k < N; k += stride) g_cnt[k] = 0.f;
        float2* p2 = reinterpret_cast<float2*>(g_spq);
        float2 z2 = make_float2(0.f, 0.f);
        for (int k = i; k < N; k += stride) p2[k] = z2;
        return;
    }
    if (b == 0) {
        for (int k = 0; k < IN_X; k++) {
            float s = 0.f;
            for (int m = 0; m < IN_E; m++) s += W0[k * IN_E + m] * W1l[m * HID + j];
            g_W0l[k * HID + j] = s;
        }
        float s = 0.f;
        for (int m = 0; m < IN_E; m++) s += b0[m] * W1l[m * HID + j];
        g_c0l[j] = s;
    } else if (b == 1) {
        for (int k = 0; k < IN_X; k++) {
            float s = 0.f;
            for (int m = 0; m < IN_E; m++) s += W0[k * IN_E + m] * W1r[m * HID + j];
            g_W0r[k * HID + j] = s;
        }
        float s = 0.f;
        for (int m = 0; m < IN_E; m++) s += b0[m] * W1r[m * HID + j];
        g_c1[j] = b1l[j] + s;
    } else if (b == 2) {
        float sa = 0.f, sb = 0.f;
        for (int t = 0; t < OUT; t++) {
            float w = W2l[j * OUT + t];
            sa += w * Wp[t];
            sb += w * Wp[OUT + t];
        }
        g_val[j] = sa; g_vbl[j] = sb;
        if (j == 0) {
            float ca = 0.f, cb = 0.f;
            for (int t = 0; t < OUT; t++) { ca += b2l[t] * Wp[t]; cb += b2l[t] * Wp[OUT + t]; }
            g_cab[0] = ca + bp[0];
            g_cab[1] = cb;
        }
    } else {
        float sa = 0.f, sb = 0.f;
        for (int t = 0; t < OUT; t++) {
            float w = W2r[j * OUT + t];
            sa += w * Wp[t];
            sb += w * Wp[OUT + t];
        }
        g_var[j] = sa; g_vbr[j] = sb;
    }
}

// ---------------------------------------------------------------------------
// Vector no-return reductions (sm_90+)
// ---------------------------------------------------------------------------
__device__ __forceinline__ void red_add_v4(float* p, float4 v) {
    asm volatile("red.global.add.v4.f32 [%0], {%1, %2, %3, %4};"
                 :: "l"(p), "f"(v.x), "f"(v.y), "f"(v.z), "f"(v.w) : "memory");
}
__device__ __forceinline__ void red_add_v2(float* p, float2 v) {
    asm volatile("red.global.add.v2.f32 [%0], {%1, %2};"
                 :: "l"(p), "f"(v.x), "f"(v.y) : "memory");
}

// ---------------------------------------------------------------------------
// Scatter 1: ssumx[dst] += x[src] (32-dim, 8 threads/edge), cnt[dst] += 1
// ---------------------------------------------------------------------------
__global__ void k_scatter1(const float* __restrict__ x,
                           const int* __restrict__ src,
                           const int* __restrict__ dst, int E) {
    int gid = blockIdx.x * blockDim.x + threadIdx.x;
    int e = gid >> 3;
    int c = gid & 7;
    if (e >= E) return;
    int s = src[e];
    int d = dst[e];
    float4 v = *reinterpret_cast<const float4*>(x + (size_t)s * IN_X + c * 4);
    red_add_v4(g_ssumx + (size_t)d * IN_X + c * 4, v);
    if (c == 0) atomicAdd(g_cnt + d, 1.0f);
}

// ---------------------------------------------------------------------------
// TF32 helpers: round-to-nearest tf32 + hi/lo split, and m16n8k8 mma.
// ---------------------------------------------------------------------------
__device__ __forceinline__ unsigned f2tf(float f) {
    unsigned u;
    asm("cvt.rna.tf32.f32 %0, %1;" : "=r"(u) : "f"(f));
    return u;
}
__device__ __forceinline__ void split_tf(float f, unsigned& hi, unsigned& lo) {
    hi = f2tf(f);
    lo = f2tf(f - __uint_as_float(hi));
}
__device__ __forceinline__ void mma_tf32(float* c, const unsigned* a,
                                         unsigned b0, unsigned b1) {
    asm volatile(
        "mma.sync.aligned.m16n8k8.row.col.f32.tf32.tf32.f32 "
        "{%0,%1,%2,%3}, {%4,%5,%6,%7}, {%8,%9}, {%0,%1,%2,%3};"
        : "+f"(c[0]), "+f"(c[1]), "+f"(c[2]), "+f"(c[3])
        : "r"(a[0]), "r"(a[1]), "r"(a[2]), "r"(a[3]), "r"(b0), "r"(b1));
}

// ---------------------------------------------------------------------------
// SAGE1 (folded) via 3xTF32 tensor-core MMA:
//   D[32x128] = A[32x64] @ W[64x128],  A = [meanx | x],  W = [W0l ; W0r]
//   h1 = relu(D + c1 + flag*c0l); p,q,ra,rb = h1 . {val,vbl,var,vbr}
// Block = 128 thr / 4 warps / 32 nodes. Warp w: m-tile (w&1), n-half (w>>1).
// A padded to 68 floats/row, W to 136 -> conflict-free fragment LDS.
// ---------------------------------------------------------------------------
#define S1_NODES 32
__global__ void __launch_bounds__(128) k_sage1(const float* __restrict__ x, int N) {
    __shared__ float sA[32 * 68];     // 8704 B
    __shared__ float sW[64 * 136];    // 34816 B
    __shared__ float sC[6 * 128];     // c1,c0l,val,vbl,var,vbr  3072 B
    __shared__ float sflag[32];
    __shared__ float sinv[32];
    __shared__ float part[32][4][2];  // [node][quantity][n-half]

    int tid = threadIdx.x;
    int lane = tid & 31, w = tid >> 5;
    int g = lane >> 2, tg = lane & 3;
    int mt = w & 1, nh = w >> 1;
    int n0 = blockIdx.x * S1_NODES;

    // stage W[64][136]: rows 0-31 = W0l, rows 32-63 = W0r (float4 fills)
    {
        const float4* Wl4 = reinterpret_cast<const float4*>(g_W0l);
        const float4* Wr4 = reinterpret_cast<const float4*>(g_W0r);
        for (int i = tid; i < 64 * 32; i += 128) {
            int k = i >> 5, j4 = i & 31;
            float4 v = (k < 32) ? Wl4[k * 32 + j4] : Wr4[(k - 32) * 32 + j4];
            *reinterpret_cast<float4*>(&sW[k * 136 + j4 * 4]) = v;
        }
    }
    // stage constants
    sC[tid]       = g_c1[tid];
    sC[128 + tid] = g_c0l[tid];
    sC[256 + tid] = g_val[tid];
    sC[384 + tid] = g_vbl[tid];
    sC[512 + tid] = g_var[tid];
    sC[640 + tid] = g_vbr[tid];
    // stage per-node cnt
    if (tid < 32) {
        float c = (n0 + tid < N) ? g_cnt[n0 + tid] : 0.f;
        sinv[tid]  = 1.0f / fmaxf(c, 1.0f);
        sflag[tid] = (c > 0.f) ? 1.0f : 0.0f;
    }
    __syncthreads();

    // stage A[32][68]: cols 0-31 = meanx (scaled), 32-63 = x, 64-67 pad
    for (int i = tid; i < 32 * 16; i += 128) {
        int nn = i >> 4, q = i & 15;
        int row = n0 + nn;
        float4 v = make_float4(0.f, 0.f, 0.f, 0.f);
        if (row < N) {
            if (q < 8) {
                float inv = sinv[nn];
                v = *reinterpret_cast<const float4*>(g_ssumx + (size_t)row * IN_X + q * 4);
                v.x *= inv; v.y *= inv; v.z *= inv; v.w *= inv;
            } else {
                v = *reinterpret_cast<const float4*>(x + (size_t)row * IN_X + (q - 8) * 4);
            }
        }
        *reinterpret_cast<float4*>(&sA[nn * 68 + q * 4]) = v;
    }
    __syncthreads();

    // main loop: 8 k-steps x 8 n-tiles, 3 mmas each (hi*hi, hi*lo, lo*hi)
    float acc[8][4];
#pragma unroll
    for (int t = 0; t < 8; t++) {
        acc[t][0] = 0.f; acc[t][1] = 0.f; acc[t][2] = 0.f; acc[t][3] = 0.f;
    }

    const int arow0 = (mt * 16 + g) * 68;
    const int arow1 = (mt * 16 + g + 8) * 68;
    const int nbase = nh * 64 + g;

#pragma unroll
    for (int kk = 0; kk < 8; kk++) {
        int k0 = kk * 8;
        float a0f = sA[arow0 + k0 + tg];
        float a1f = sA[arow1 + k0 + tg];
        float a2f = sA[arow0 + k0 + tg + 4];
        float a3f = sA[arow1 + k0 + tg + 4];
        unsigned ah[4], al[4];
        split_tf(a0f, ah[0], al[0]);
        split_tf(a1f, ah[1], al[1]);
        split_tf(a2f, ah[2], al[2]);
        split_tf(a3f, ah[3], al[3]);
        const float* wr0 = &sW[(k0 + tg) * 136 + nbase];
        const float* wr1 = &sW[(k0 + tg + 4) * 136 + nbase];
#pragma unroll
        for (int t = 0; t < 8; t++) {
            float b0f = wr0[t * 8];
            float b1f = wr1[t * 8];
            unsigned bh0, bl0, bh1, bl1;
            split_tf(b0f, bh0, bl0);
            split_tf(b1f, bh1, bl1);
            mma_tf32(acc[t], ah, bh0, bh1);
            mma_tf32(acc[t], ah, bl0, bl1);
            mma_tf32(acc[t], al, bh0, bh1);
        }
    }

    // epilogue: relu + 4 projections, per-thread partials over 16 owned cols
    float flag0 = sflag[mt * 16 + g];
    float flag1 = sflag[mt * 16 + g + 8];
    float pa0 = 0.f, pb0 = 0.f, ra0 = 0.f, rb0 = 0.f;
    float pa1 = 0.f, pb1 = 0.f, ra1 = 0.f, rb1 = 0.f;
#pragma unroll
    for (int t = 0; t < 8; t++) {
        int col0 = nh * 64 + t * 8 + 2 * tg;
        float c1a = sC[col0],       c1b = sC[col0 + 1];
        float c0a = sC[128 + col0], c0b = sC[128 + col0 + 1];
        float va  = sC[256 + col0], vb  = sC[256 + col0 + 1];
        float vba = sC[384 + col0], vbb = sC[384 + col0 + 1];
        float wa  = sC[512 + col0], wb  = sC[512 + col0 + 1];
        float wba = sC[640 + col0], wbb = sC[640 + col0 + 1];
        float h00 = fmaxf(acc[t][0] + c1a + flag0 * c0a, 0.f);
        float h01 = fmaxf(acc[t][1] + c1b + flag0 * c0b, 0.f);
        float h10 = fmaxf(acc[t][2] + c1a + flag1 * c0a, 0.f);
        float h11 = fmaxf(acc[t][3] + c1b + flag1 * c0b, 0.f);
        pa0 += h00 * va  + h01 * vb;
        pb0 += h00 * vba + h01 * vbb;
        ra0 += h00 * wa  + h01 * wb;
        rb0 += h00 * wba + h01 * wbb;
        pa1 += h10 * va  + h11 * vb;
        pb1 += h10 * vba + h11 * vbb;
        ra1 += h10 * wa  + h11 * wb;
        rb1 += h10 * wba + h11 * wbb;
    }
    // reduce across the 4 lanes sharing g (xor in low 2 bits)
#pragma unroll
    for (int off = 1; off < 4; off <<= 1) {
        pa0 += __shfl_xor_sync(0xffffffffu, pa0, off);
        pb0 += __shfl_xor_sync(0xffffffffu, pb0, off);
        ra0 += __shfl_xor_sync(0xffffffffu, ra0, off);
        rb0 += __shfl_xor_sync(0xffffffffu, rb0, off);
        pa1 += __shfl_xor_sync(0xffffffffu, pa1, off);
        pb1 += __shfl_xor_sync(0xffffffffu, pb1, off);
        ra1 += __shfl_xor_sync(0xffffffffu, ra1, off);
        rb1 += __shfl_xor_sync(0xffffffffu, rb1, off);
    }
    if (tg == 0) {
        int nn0 = mt * 16 + g, nn1 = nn0 + 8;
        part[nn0][0][nh] = pa0; part[nn0][1][nh] = pb0;
        part[nn0][2][nh] = ra0; part[nn0][3][nh] = rb0;
        part[nn1][0][nh] = pa1; part[nn1][1][nh] = pb1;
        part[nn1][2][nh] = ra1; part[nn1][3][nh] = rb1;
    }
    __syncthreads();

    // combine n-halves and write per-node scalars
    {
        int nn = tid >> 2, q = tid & 3;
        int row = n0 + nn;
        if (row < N) {
            float s = part[nn][q][0] + part[nn][q][1];
            if (q == 0)      g_pq[2 * (size_t)row]     = s;
            else if (q == 1) g_pq[2 * (size_t)row + 1] = s;
            else if (q == 2) g_r[2 * (size_t)row]      = s;
            else             g_r[2 * (size_t)row + 1]  = s;
        }
    }
}

// ---------------------------------------------------------------------------
// Scatter 2 (scalar): spq[dst] += pq[src]   — one thread/edge, 8B red.
// ---------------------------------------------------------------------------
__global__ void k_scatter2(const int* __restrict__ src,
                           const int* __restrict__ dst, int E) {
    int e = blockIdx.x * blockDim.x + threadIdx.x;
    if (e >= E) return;
    int s = src[e];
    int d = dst[e];
    float2 v = *reinterpret_cast<const float2*>(g_pq + 2 * (size_t)s);
    red_add_v2(g_spq + 2 * (size_t)d, v);
}

// ---------------------------------------------------------------------------
// Finish: a = spq.x/max(cnt,1) + cab.x + ra ;  b = spq.y/max(cnt,1) + cab.y + rb
// ---------------------------------------------------------------------------
__global__ void k_finish(int N) {
    int n = blockIdx.x * blockDim.x + threadIdx.x;
    if (n >= N) return;
    float inv = 1.0f / fmaxf(g_cnt[n], 1.0f);
    float2 spq = *reinterpret_cast<const float2*>(g_spq + 2 * (size_t)n);
    float2 r   = *reinterpret_cast<const float2*>(g_r   + 2 * (size_t)n);
    float2 ab;
    ab.x = spq.x * inv + g_cab[0] + r.x;
    ab.y = spq.y * inv + g_cab[1] + r.y;
    *reinterpret_cast<float2*>(g_ab + 2 * (size_t)n) = ab;
}

// ---------------------------------------------------------------------------
// Pred: raw[e] = a[src] + b[dst]; out = {raw, sigmoid(raw)}. 4 edges/thread.
// ---------------------------------------------------------------------------
__global__ void k_pred(const int* __restrict__ src,
                       const int* __restrict__ dst,
                       float* __restrict__ out, int E) {
    int t = blockIdx.x * blockDim.x + threadIdx.x;
    int e0 = t * 4;
    if (e0 >= E) return;
    if (e0 + 3 < E) {
        int4 s4 = *reinterpret_cast<const int4*>(src + e0);
        int4 d4 = *reinterpret_cast<const int4*>(dst + e0);
        float r0 = g_ab[2 * (size_t)s4.x] + g_ab[2 * (size_t)d4.x + 1];
        float r1 = g_ab[2 * (size_t)s4.y] + g_ab[2 * (size_t)d4.y + 1];
        float r2 = g_ab[2 * (size_t)s4.z] + g_ab[2 * (size_t)d4.z + 1];
        float r3 = g_ab[2 * (size_t)s4.w] + g_ab[2 * (size_t)d4.w + 1];
        *reinterpret_cast<float4*>(out + e0) = make_float4(r0, r1, r2, r3);
        float g0 = 1.0f / (1.0f + __expf(-r0));
        float g1 = 1.0f / (1.0f + __expf(-r1));
        float g2 = 1.0f / (1.0f + __expf(-r2));
        float g3 = 1.0f / (1.0f + __expf(-r3));
        *reinterpret_cast<float4*>(out + (size_t)E + e0) = make_float4(g0, g1, g2, g3);
    } else {
        for (int e = e0; e < E; e++) {
            float r0 = g_ab[2 * (size_t)src[e]] + g_ab[2 * (size_t)dst[e] + 1];
            out[e] = r0;
            out[(size_t)E + e] = 1.0f / (1.0f + __expf(-r0));
        }
    }
}

// ---------------------------------------------------------------------------
// Launch
// ---------------------------------------------------------------------------
extern "C" void kernel_launch(void* const* d_in, const int* in_sizes, int n_in,
                              void* d_out, int out_size) {
    const float* x   = (const float*)d_in[0];
    const int*   ei  = (const int*)d_in[1];
    const float* W0  = (const float*)d_in[2];
    const float* b0  = (const float*)d_in[3];
    const float* W1l = (const float*)d_in[4];
    const float* b1l = (const float*)d_in[5];
    const float* W1r = (const float*)d_in[6];
    const float* W2l = (const float*)d_in[7];
    const float* b2l = (const float*)d_in[8];
    const float* W2r = (const float*)d_in[9];
    const float* Wp  = (const float*)d_in[10];
    const float* bp  = (const float*)d_in[11];
    float* out = (float*)d_out;

    int N = in_sizes[0] / IN_X;   // 100000
    int E = in_sizes[1] / 2;      // 2000000
    const int* src = ei;
    const int* dst = ei + E;

    k_prep_zero<<<4 + 2368, 128>>>(W0, b0, W1l, b1l, W1r, W2l, b2l, W2r, Wp, bp, N);

    {   // scatter1: 8 threads/edge (coalesced row coverage)
        long long t = (long long)E * 8;
        int blocks = (int)((t + 255) / 256);
        k_scatter1<<<blocks, 256>>>(x, src, dst, E);
    }
    k_sage1<<<(N + S1_NODES - 1) / S1_NODES, 128>>>(x, N);
    k_scatter2<<<(E + 255) / 256, 256>>>(src, dst, E);
    k_finish<<<(N + 255) / 256, 256>>>(N);
    k_pred<<<(E / 4 + 255) / 256, 256>>>(src, dst, out, E);
}

// round 17
// speedup vs baseline: 1.0357x; 1.0357x over previous
#include <cuda_runtime.h>
#include <math.h>

// Problem-fixed dims
#define NN 100000
#define IN_X 32
#define IN_E 64
#define HID 128
#define OUT 64

// ---- folded weights (computed by k_prep every launch; deterministic) ----
__device__ __align__(16) float g_W0l[IN_X * HID];  // W0 @ W1l
__device__ __align__(16) float g_W0r[IN_X * HID];  // W0 @ W1r
__device__ __align__(16) float g_c0l[HID];         // b0 @ W1l (gated by cnt>0)
__device__ __align__(16) float g_c1[HID];          // b1l + b0 @ W1r
__device__ __align__(16) float g_val[HID];         // W2l @ Wp[0:64]
__device__ __align__(16) float g_vbl[HID];         // W2l @ Wp[64:128]
__device__ __align__(16) float g_var[HID];         // W2r @ Wp[0:64]
__device__ __align__(16) float g_vbr[HID];         // W2r @ Wp[64:128]
__device__ float g_cab[2];   // b2l.Wpa + bp, b2l.Wpb   (bp folded in)

// ---- per-node scratch ----
__device__ __align__(16) float g_ssumx[NN * IN_X]; // scatter of raw x
__device__ __align__(16) float g_cnt[NN];
__device__ __align__(16) float g_pq[2 * NN];       // p,q  -> scatter source
__device__ __align__(16) float g_r[2 * NN];        // ra,rb (self term)
__device__ __align__(16) float g_spq[2 * NN];      // scattered sums of p,q
__device__ __align__(16) float g_ab[2 * NN];       // final per-node scalars

// ---------------------------------------------------------------------------
// Prep + zero fused: blocks 0-3 fold weights; blocks >=4 zero accumulators.
// ---------------------------------------------------------------------------
__global__ void k_prep_zero(const float* __restrict__ W0, const float* __restrict__ b0,
                            const float* __restrict__ W1l, const float* __restrict__ b1l,
                            const float* __restrict__ W1r,
                            const float* __restrict__ W2l, const float* __restrict__ b2l,
                            const float* __restrict__ W2r,
                            const float* __restrict__ Wp, const float* __restrict__ bp,
                            int N) {
    int b = blockIdx.x;
    int j = threadIdx.x;   // 0..127
    if (b >= 4) {
        int i = (b - 4) * 128 + j;
        int stride = (gridDim.x - 4) * 128;
        int n1 = (N * IN_X) / 4;
        float4 z = make_float4(0.f, 0.f, 0.f, 0.f);
        float4* p1 = reinterpret_cast<float4*>(g_ssumx);
        for (int k = i; k < n1; k += stride) p1[k] = z;
        for (int k = i; k < N; k += stride) g_cnt[k] = 0.f;
        float2* p2 = reinterpret_cast<float2*>(g_spq);
        float2 z2 = make_float2(0.f, 0.f);
        for (int k = i; k < N; k += stride) p2[k] = z2;
        return;
    }
    if (b == 0) {
        for (int k = 0; k < IN_X; k++) {
            float s = 0.f;
            for (int m = 0; m < IN_E; m++) s += W0[k * IN_E + m] * W1l[m * HID + j];
            g_W0l[k * HID + j] = s;
        }
        float s = 0.f;
        for (int m = 0; m < IN_E; m++) s += b0[m] * W1l[m * HID + j];
        g_c0l[j] = s;
    } else if (b == 1) {
        for (int k = 0; k < IN_X; k++) {
            float s = 0.f;
            for (int m = 0; m < IN_E; m++) s += W0[k * IN_E + m] * W1r[m * HID + j];
            g_W0r[k * HID + j] = s;
        }
        float s = 0.f;
        for (int m = 0; m < IN_E; m++) s += b0[m] * W1r[m * HID + j];
        g_c1[j] = b1l[j] + s;
    } else if (b == 2) {
        float sa = 0.f, sb = 0.f;
        for (int t = 0; t < OUT; t++) {
            float w = W2l[j * OUT + t];
            sa += w * Wp[t];
            sb += w * Wp[OUT + t];
        }
        g_val[j] = sa; g_vbl[j] = sb;
        if (j == 0) {
            float ca = 0.f, cb = 0.f;
            for (int t = 0; t < OUT; t++) { ca += b2l[t] * Wp[t]; cb += b2l[t] * Wp[OUT + t]; }
            g_cab[0] = ca + bp[0];
            g_cab[1] = cb;
        }
    } else {
        float sa = 0.f, sb = 0.f;
        for (int t = 0; t < OUT; t++) {
            float w = W2r[j * OUT + t];
            sa += w * Wp[t];
            sb += w * Wp[OUT + t];
        }
        g_var[j] = sa; g_vbr[j] = sb;
    }
}

// ---------------------------------------------------------------------------
// Vector no-return reductions (sm_90+)
// ---------------------------------------------------------------------------
__device__ __forceinline__ void red_add_v4(float* p, float4 v) {
    asm volatile("red.global.add.v4.f32 [%0], {%1, %2, %3, %4};"
                 :: "l"(p), "f"(v.x), "f"(v.y), "f"(v.z), "f"(v.w) : "memory");
}
__device__ __forceinline__ void red_add_v2(float* p, float2 v) {
    asm volatile("red.global.add.v2.f32 [%0], {%1, %2};"
                 :: "l"(p), "f"(v.x), "f"(v.y) : "memory");
}

// ---------------------------------------------------------------------------
// Scatter 1: ssumx[dst] += x[src] (32-dim, 8 threads/edge), cnt[dst] += 1
// 8 consecutive lanes cover one 128-B row -> coalesced wavefronts (R14 lesson:
// 1 thread/edge fragments every instruction into 32 sectors and is 2x slower).
// ---------------------------------------------------------------------------
__global__ void k_scatter1(const float* __restrict__ x,
                           const int* __restrict__ src,
                           const int* __restrict__ dst, int E) {
    int gid = blockIdx.x * blockDim.x + threadIdx.x;
    int e = gid >> 3;
    int c = gid & 7;
    if (e >= E) return;
    int s = src[e];
    int d = dst[e];
    float4 v = *reinterpret_cast<const float4*>(x + (size_t)s * IN_X + c * 4);
    red_add_v4(g_ssumx + (size_t)d * IN_X + c * 4, v);
    if (c == 0) atomicAdd(g_cnt + d, 1.0f);
}

// ---------------------------------------------------------------------------
// SAGE1 (folded), shuffle-free inner loop — measured-best configuration:
//   h1 = relu( meanx @ W0l + flag*c0l + c1 + x @ W0r )   (in registers)
//   p=h1.val, q=h1.vbl -> g_pq ;  ra=h1.var, rb=h1.vbr -> g_r
// Block = 128 thr / 4 warps / 32 nodes. Warp owns 8 nodes; lane owns 4 cols.
// (R16: TF32 tensor-core version is correct but 6 us slower — split overhead.)
// ---------------------------------------------------------------------------
#define S1_NODES 32
__global__ void __launch_bounds__(128) k_sage1(const float* __restrict__ x, int N) {
    __shared__ float4 sWl[IN_X][32];     // [k][lane] 16 KB
    __shared__ float4 sWr[IN_X][32];     // 16 KB
    __shared__ float smx[32][IN_X];      // mean-agg features, 4 KB
    __shared__ float ssx[32][IN_X];      // self features, 4 KB
    __shared__ float sinv[32];
    __shared__ float sflag[32];

    int tid = threadIdx.x;
    int lane = tid & 31, wid = tid >> 5;
    int n0 = blockIdx.x * 32;

    // stage folded weights (1024 float4 each)
    {
        const float4* Wl4 = reinterpret_cast<const float4*>(g_W0l);
        const float4* Wr4 = reinterpret_cast<const float4*>(g_W0r);
        for (int i = tid; i < IN_X * 32; i += 128) {
            sWl[i >> 5][i & 31] = Wl4[i];
            sWr[i >> 5][i & 31] = Wr4[i];
        }
    }
    // stage per-node cnt
    if (tid < 32) {
        float c = (n0 + tid < N) ? g_cnt[n0 + tid] : 0.f;
        sinv[tid]  = 1.0f / fmaxf(c, 1.0f);
        sflag[tid] = (c > 0.f) ? 1.0f : 0.0f;
    }
    __syncthreads();

    // stage node features: 32 nodes x 8 float4 per array
    for (int i = tid; i < 32 * 8; i += 128) {
        int n = i >> 3, k4 = (i & 7) * 4;
        int row = n0 + n;
        float4 vm = make_float4(0.f, 0.f, 0.f, 0.f);
        float4 vs = vm;
        if (row < N) {
            float inv = sinv[n];
            vm = *reinterpret_cast<const float4*>(g_ssumx + (size_t)row * IN_X + k4);
            vm.x *= inv; vm.y *= inv; vm.z *= inv; vm.w *= inv;
            vs = *reinterpret_cast<const float4*>(x + (size_t)row * IN_X + k4);
        }
        *reinterpret_cast<float4*>(&smx[n][k4]) = vm;
        *reinterpret_cast<float4*>(&ssx[n][k4]) = vs;
    }
    __syncthreads();

    int nb = wid * 8;   // this warp's first node (in-block)
    float4 acc[8];
#pragma unroll
    for (int n = 0; n < 8; n++) acc[n] = make_float4(0.f, 0.f, 0.f, 0.f);

#pragma unroll 2
    for (int k = 0; k < IN_X; k += 4) {
        float4 wl0 = sWl[k + 0][lane];
        float4 wl1 = sWl[k + 1][lane];
        float4 wl2 = sWl[k + 2][lane];
        float4 wl3 = sWl[k + 3][lane];
        float4 wr0 = sWr[k + 0][lane];
        float4 wr1 = sWr[k + 1][lane];
        float4 wr2 = sWr[k + 2][lane];
        float4 wr3 = sWr[k + 3][lane];
#pragma unroll
        for (int n = 0; n < 8; n++) {
            float4 a = *reinterpret_cast<const float4*>(&smx[nb + n][k]);   // broadcast
            float4 h = *reinterpret_cast<const float4*>(&ssx[nb + n][k]);   // broadcast
            acc[n].x += a.x * wl0.x + a.y * wl1.x + a.z * wl2.x + a.w * wl3.x
                      + h.x * wr0.x + h.y * wr1.x + h.z * wr2.x + h.w * wr3.x;
            acc[n].y += a.x * wl0.y + a.y * wl1.y + a.z * wl2.y + a.w * wl3.y
                      + h.x * wr0.y + h.y * wr1.y + h.z * wr2.y + h.w * wr3.y;
            acc[n].z += a.x * wl0.z + a.y * wl1.z + a.z * wl2.z + a.w * wl3.z
                      + h.x * wr0.z + h.y * wr1.z + h.z * wr2.z + h.w * wr3.z;
            acc[n].w += a.x * wl0.w + a.y * wl1.w + a.z * wl2.w + a.w * wl3.w
                      + h.x * wr0.w + h.y * wr1.w + h.z * wr2.w + h.w * wr3.w;
        }
    }

    // epilogue: bias + relu + 4 scalar projections per node, warp-reduced
    float4 c1v  = reinterpret_cast<const float4*>(g_c1)[lane];
    float4 c0v  = reinterpret_cast<const float4*>(g_c0l)[lane];
    float4 valv = reinterpret_cast<const float4*>(g_val)[lane];
    float4 vblv = reinterpret_cast<const float4*>(g_vbl)[lane];
    float4 varv = reinterpret_cast<const float4*>(g_var)[lane];
    float4 vbrv = reinterpret_cast<const float4*>(g_vbr)[lane];

#pragma unroll
    for (int n = 0; n < 8; n++) {
        float flag = sflag[nb + n];
        float hx = fmaxf(acc[n].x + c1v.x + flag * c0v.x, 0.f);
        float hy = fmaxf(acc[n].y + c1v.y + flag * c0v.y, 0.f);
        float hz = fmaxf(acc[n].z + c1v.z + flag * c0v.z, 0.f);
        float hw = fmaxf(acc[n].w + c1v.w + flag * c0v.w, 0.f);
        float pa = hx * valv.x + hy * valv.y + hz * valv.z + hw * valv.w;
        float pb = hx * vblv.x + hy * vblv.y + hz * vblv.z + hw * vblv.w;
        float ra = hx * varv.x + hy * varv.y + hz * varv.z + hw * varv.w;
        float rb = hx * vbrv.x + hy * vbrv.y + hz * vbrv.z + hw * vbrv.w;
#pragma unroll
        for (int o = 16; o > 0; o >>= 1) {
            pa += __shfl_down_sync(0xffffffffu, pa, o);
            pb += __shfl_down_sync(0xffffffffu, pb, o);
            ra += __shfl_down_sync(0xffffffffu, ra, o);
            rb += __shfl_down_sync(0xffffffffu, rb, o);
        }
        int row = n0 + nb + n;
        if (lane == 0 && row < N) {
            *reinterpret_cast<float2*>(g_pq + 2 * (size_t)row) = make_float2(pa, pb);
            *reinterpret_cast<float2*>(g_r  + 2 * (size_t)row) = make_float2(ra, rb);
        }
    }
}

// ---------------------------------------------------------------------------
// Scatter 2 (scalar): spq[dst] += pq[src]   — one thread/edge, 8B red.
// ---------------------------------------------------------------------------
__global__ void k_scatter2(const int* __restrict__ src,
                           const int* __restrict__ dst, int E) {
    int e = blockIdx.x * blockDim.x + threadIdx.x;
    if (e >= E) return;
    int s = src[e];
    int d = dst[e];
    float2 v = *reinterpret_cast<const float2*>(g_pq + 2 * (size_t)s);
    red_add_v2(g_spq + 2 * (size_t)d, v);
}

// ---------------------------------------------------------------------------
// Finish: a = spq.x/max(cnt,1) + cab.x + ra ;  b = spq.y/max(cnt,1) + cab.y + rb
// ---------------------------------------------------------------------------
__global__ void k_finish(int N) {
    int n = blockIdx.x * blockDim.x + threadIdx.x;
    if (n >= N) return;
    float inv = 1.0f / fmaxf(g_cnt[n], 1.0f);
    float2 spq = *reinterpret_cast<const float2*>(g_spq + 2 * (size_t)n);
    float2 r   = *reinterpret_cast<const float2*>(g_r   + 2 * (size_t)n);
    float2 ab;
    ab.x = spq.x * inv + g_cab[0] + r.x;
    ab.y = spq.y * inv + g_cab[1] + r.y;
    *reinterpret_cast<float2*>(g_ab + 2 * (size_t)n) = ab;
}

// ---------------------------------------------------------------------------
// Pred: raw[e] = a[src] + b[dst]; out = {raw, sigmoid(raw)}. 4 edges/thread.
// ---------------------------------------------------------------------------
__global__ void k_pred(const int* __restrict__ src,
                       const int* __restrict__ dst,
                       float* __restrict__ out, int E) {
    int t = blockIdx.x * blockDim.x + threadIdx.x;
    int e0 = t * 4;
    if (e0 >= E) return;
    if (e0 + 3 < E) {
        int4 s4 = *reinterpret_cast<const int4*>(src + e0);
        int4 d4 = *reinterpret_cast<const int4*>(dst + e0);
        float r0 = g_ab[2 * (size_t)s4.x] + g_ab[2 * (size_t)d4.x + 1];
        float r1 = g_ab[2 * (size_t)s4.y] + g_ab[2 * (size_t)d4.y + 1];
        float r2 = g_ab[2 * (size_t)s4.z] + g_ab[2 * (size_t)d4.z + 1];
        float r3 = g_ab[2 * (size_t)s4.w] + g_ab[2 * (size_t)d4.w + 1];
        *reinterpret_cast<float4*>(out + e0) = make_float4(r0, r1, r2, r3);
        float g0 = 1.0f / (1.0f + __expf(-r0));
        float g1 = 1.0f / (1.0f + __expf(-r1));
        float g2 = 1.0f / (1.0f + __expf(-r2));
        float g3 = 1.0f / (1.0f + __expf(-r3));
        *reinterpret_cast<float4*>(out + (size_t)E + e0) = make_float4(g0, g1, g2, g3);
    } else {
        for (int e = e0; e < E; e++) {
            float r0 = g_ab[2 * (size_t)src[e]] + g_ab[2 * (size_t)dst[e] + 1];
            out[e] = r0;
            out[(size_t)E + e] = 1.0f / (1.0f + __expf(-r0));
        }
    }
}

// ---------------------------------------------------------------------------
// Launch
// ---------------------------------------------------------------------------
extern "C" void kernel_launch(void* const* d_in, const int* in_sizes, int n_in,
                              void* d_out, int out_size) {
    const float* x   = (const float*)d_in[0];
    const int*   ei  = (const int*)d_in[1];
    const float* W0  = (const float*)d_in[2];
    const float* b0  = (const float*)d_in[3];
    const float* W1l = (const float*)d_in[4];
    const float* b1l = (const float*)d_in[5];
    const float* W1r = (const float*)d_in[6];
    const float* W2l = (const float*)d_in[7];
    const float* b2l = (const float*)d_in[8];
    const float* W2r = (const float*)d_in[9];
    const float* Wp  = (const float*)d_in[10];
    const float* bp  = (const float*)d_in[11];
    float* out = (float*)d_out;

    int N = in_sizes[0] / IN_X;   // 100000
    int E = in_sizes[1] / 2;      // 2000000
    const int* src = ei;
    const int* dst = ei + E;

    k_prep_zero<<<4 + 2368, 128>>>(W0, b0, W1l, b1l, W1r, W2l, b2l, W2r, Wp, bp, N);

    {   // scatter1: 8 threads/edge (coalesced row coverage)
        long long t = (long long)E * 8;
        int blocks = (int)((t + 255) / 256);
        k_scatter1<<<blocks, 256>>>(x, src, dst, E);
    }
    k_sage1<<<(N + S1_NODES - 1) / S1_NODES, 128>>>(x, N);
    k_scatter2<<<(E + 255) / 256, 256>>>(src, dst, E);
    k_finish<<<(N + 255) / 256, 256>>>(N);
    k_pred<<<(E / 4 + 255) / 256, 256>>>(src, dst, out, E);
}